// round 3
// baseline (speedup 1.0000x reference)
#include <cuda_runtime.h>
#include <cstddef>

// Problem constants
static constexpr int Bb    = 4;
static constexpr int Nn    = 4096;
static constexpr int Dd    = 1024;
static constexpr int Mrows = Bb * Nn;      // 16384
static constexpr int QKVN  = 3 * Dd;       // 3072

// Scratch (alloc-free rule: __device__ globals).
// Attention output is written IN PLACE into the q-region of g_qkv,
// so no second scratch buffer is needed.
__device__ float g_qkv[(size_t)Mrows * QKVN];   // ~201 MB

// ---------------------------------------------------------------------------
// SGEMM (NT): C[m][n] = sum_k A[m*lda + k] * W[n*Kdim + k]  (+ bias[n])
// BM=BN=128, BK=16, 256 threads, 8x8 microtile, float4 global loads,
// transposed smem tiles, software-pipelined global->reg prefetch.
// Requires M%128==0, N%128==0, K%16==0 (holds for all our shapes).
// ---------------------------------------------------------------------------
template <bool BIAS>
__global__ __launch_bounds__(256)
void sgemm_nt(const float* __restrict__ A, const float* __restrict__ W,
              const float* __restrict__ bias, float* __restrict__ C,
              int Ndim, int Kdim, int lda)
{
    constexpr int BM = 128, BN = 128, BK = 16;
    __shared__ float As[BK][BM + 4];
    __shared__ float Ws[BK][BN + 4];

    const int tid = threadIdx.x;
    const int tx  = tid & 15;        // 0..15 -> n microtile
    const int ty  = tid >> 4;        // 0..15 -> m microtile
    const int m0  = blockIdx.y * BM;
    const int n0  = blockIdx.x * BN;

    const int lrow = tid >> 2;        // 0..63
    const int lcol = (tid & 3) * 4;   // 0,4,8,12

    const float* Ag = A + (size_t)(m0 + lrow) * lda  + lcol;
    const float* Wg = W + (size_t)(n0 + lrow) * Kdim + lcol;

    float acc[8][8];
    #pragma unroll
    for (int i = 0; i < 8; ++i)
        #pragma unroll
        for (int j = 0; j < 8; ++j) acc[i][j] = 0.f;

    float4 pa[2], pw[2];

    // --- first k-tile straight to smem ---
    #pragma unroll
    for (int r = 0; r < 2; ++r) {
        const int row = lrow + r * 64;
        float4 a = *(const float4*)(Ag + (size_t)r * 64 * lda);
        float4 w = *(const float4*)(Wg + (size_t)r * 64 * Kdim);
        As[lcol + 0][row] = a.x; As[lcol + 1][row] = a.y;
        As[lcol + 2][row] = a.z; As[lcol + 3][row] = a.w;
        Ws[lcol + 0][row] = w.x; Ws[lcol + 1][row] = w.y;
        Ws[lcol + 2][row] = w.z; Ws[lcol + 3][row] = w.w;
    }

    for (int k0 = 0; k0 < Kdim; k0 += BK) {
        __syncthreads();

        const bool more = (k0 + BK) < Kdim;
        if (more) {
            #pragma unroll
            for (int r = 0; r < 2; ++r) {
                pa[r] = *(const float4*)(Ag + (size_t)r * 64 * lda  + k0 + BK);
                pw[r] = *(const float4*)(Wg + (size_t)r * 64 * Kdim + k0 + BK);
            }
        }

        #pragma unroll
        for (int kk = 0; kk < BK; ++kk) {
            float ra[8], rb[8];
            #pragma unroll
            for (int i = 0; i < 8; ++i) ra[i] = As[kk][ty * 8 + i];
            #pragma unroll
            for (int j = 0; j < 8; ++j) rb[j] = Ws[kk][tx * 8 + j];
            #pragma unroll
            for (int i = 0; i < 8; ++i)
                #pragma unroll
                for (int j = 0; j < 8; ++j)
                    acc[i][j] = fmaf(ra[i], rb[j], acc[i][j]);
        }

        __syncthreads();

        if (more) {
            #pragma unroll
            for (int r = 0; r < 2; ++r) {
                const int row = lrow + r * 64;
                As[lcol + 0][row] = pa[r].x; As[lcol + 1][row] = pa[r].y;
                As[lcol + 2][row] = pa[r].z; As[lcol + 3][row] = pa[r].w;
                Ws[lcol + 0][row] = pw[r].x; Ws[lcol + 1][row] = pw[r].y;
                Ws[lcol + 2][row] = pw[r].z; Ws[lcol + 3][row] = pw[r].w;
            }
        }
    }

    float bv[8];
    #pragma unroll
    for (int j = 0; j < 8; ++j) bv[j] = BIAS ? bias[n0 + tx * 8 + j] : 0.f;

    #pragma unroll
    for (int i = 0; i < 8; ++i) {
        const int m = m0 + ty * 8 + i;
        float* Crow = C + (size_t)m * Ndim + n0 + tx * 8;
        float4 v0 = make_float4(acc[i][0] + bv[0], acc[i][1] + bv[1],
                                acc[i][2] + bv[2], acc[i][3] + bv[3]);
        float4 v1 = make_float4(acc[i][4] + bv[4], acc[i][5] + bv[5],
                                acc[i][6] + bv[6], acc[i][7] + bv[7]);
        *(float4*)(Crow + 0) = v0;
        *(float4*)(Crow + 4) = v1;
    }
}

// ---------------------------------------------------------------------------
// Attention (the "faithful reshape" 16x16 head-mixing):
//   q_prep[b, n, h, dh] = q[b, h*256 + n/16, (n%16)*64 + dh]
//   scores[h][g] = (1/8) * sum_dh q_prep[h][dh] * k_prep[g][dh]
//   probs = softmax_g, attn[h][dh] = sum_g probs * v_prep[g][dh]
//   result written back IN PLACE over the q slice it consumed:
//   qkv[b, h*256 + n/16, (n%16)*64 + dh] = attn[h][dh]
//
// One CTA per (b, r) with r = n/16; j = n%16 looped inside. CTA (b,r) is the
// unique reader/writer of rows {b, hh*256 + r}; within the CTA the write for
// block j lands on q columns already consumed in iteration j.
// ---------------------------------------------------------------------------
__global__ __launch_bounds__(256)
void attn16_kernel(float* __restrict__ qkv)
{
    const int b = blockIdx.x >> 8;
    const int r = blockIdx.x & 255;
    const int tid = threadIdx.x;
    const int hh = tid >> 4;     // 0..15 : row index in load/out phases
    const int lo = tid & 15;     // 0..15 : d4 in load/out phases, g in score phase

    __shared__ float qs[16][64];
    __shared__ float ks[16][65];   // padded: score phase reads stride-65 rows
    __shared__ float vs[16][64];
    __shared__ float ps[16][17];

    const size_t rowbase = ((size_t)b * 4096 + (size_t)hh * 256 + r) * 3072;
    const float scale = 0.125f;  // 1/sqrt(64)

    for (int j = 0; j < 16; ++j) {
        // --- load 16x64 slices of q, k, v (cols j*64 .. j*64+63) ---
        {
            const size_t c = (size_t)j * 64 + lo * 4;
            float4 q4 = *(const float4*)(qkv + rowbase + 0    + c);
            float4 k4 = *(const float4*)(qkv + rowbase + 1024 + c);
            float4 v4 = *(const float4*)(qkv + rowbase + 2048 + c);
            *(float4*)&qs[hh][lo * 4] = q4;
            ks[hh][lo * 4 + 0] = k4.x; ks[hh][lo * 4 + 1] = k4.y;
            ks[hh][lo * 4 + 2] = k4.z; ks[hh][lo * 4 + 3] = k4.w;
            *(float4*)&vs[hh][lo * 4] = v4;
        }
        __syncthreads();

        // --- scores + softmax: thread = (h=hh, g=lo) ---
        float s = 0.f;
        #pragma unroll
        for (int d = 0; d < 64; ++d) s = fmaf(qs[hh][d], ks[lo][d], s);
        s *= scale;

        float mx = s;
        #pragma unroll
        for (int off = 8; off; off >>= 1)
            mx = fmaxf(mx, __shfl_xor_sync(0xffffffffu, mx, off, 16));
        float e = __expf(s - mx);
        float sum = e;
        #pragma unroll
        for (int off = 8; off; off >>= 1)
            sum += __shfl_xor_sync(0xffffffffu, sum, off, 16);
        ps[hh][lo] = e / sum;
        __syncthreads();

        // --- output: thread = (h=hh, d4=lo); overwrite q slice in place ---
        float4 o = make_float4(0.f, 0.f, 0.f, 0.f);
        #pragma unroll
        for (int g = 0; g < 16; ++g) {
            const float p = ps[hh][g];
            float4 v4 = *(const float4*)&vs[g][lo * 4];
            o.x = fmaf(p, v4.x, o.x); o.y = fmaf(p, v4.y, o.y);
            o.z = fmaf(p, v4.z, o.z); o.w = fmaf(p, v4.w, o.w);
        }
        *(float4*)(qkv + rowbase + (size_t)j * 64 + lo * 4) = o;
        __syncthreads();
    }
}

// ---------------------------------------------------------------------------
// Launch
// ---------------------------------------------------------------------------
extern "C" void kernel_launch(void* const* d_in, const int* in_sizes, int n_in,
                              void* d_out, int out_size)
{
    const float* x     = (const float*)d_in[0];  // (4, 4096, 1024)
    const float* w_qkv = (const float*)d_in[1];  // (3072, 1024)
    const float* w_fc  = (const float*)d_in[2];  // (1024, 1024)
    const float* b_fc  = (const float*)d_in[3];  // (1024,)
    float* out = (float*)d_out;                  // (4, 4096, 1024)

    float* qkv_ptr = nullptr;
    cudaGetSymbolAddress((void**)&qkv_ptr, g_qkv);

    dim3 blk(256);

    // 1) qkv = x @ w_qkv^T        : M=16384, N=3072, K=1024, lda=1024
    sgemm_nt<false><<<dim3(QKVN / 128, Mrows / 128), blk>>>(
        x, w_qkv, nullptr, qkv_ptr, QKVN, Dd, Dd);

    // 2) scrambled 16x16 head-mix attention, in-place into q region
    attn16_kernel<<<Bb * 256, blk>>>(qkv_ptr);

    // 3) out = attn @ w_fc^T + b_fc : M=16384, N=1024, K=1024, lda=3072
    sgemm_nt<true><<<dim3(Dd / 128, Mrows / 128), blk>>>(
        qkv_ptr, w_fc, b_fc, out, Dd, Dd, QKVN);
}

// round 4
// speedup vs baseline: 2.4832x; 2.4832x over previous
#include <cuda_runtime.h>
#include <cuda_bf16.h>
#include <cstddef>
#include <cstdint>

// Problem constants
static constexpr int Bb    = 4;
static constexpr int Nn    = 4096;
static constexpr int Dd    = 1024;
static constexpr int Mrows = Bb * Nn;      // 16384
static constexpr int QKVN  = 3 * Dd;       // 3072

// Scratch (alloc-free rule: __device__ global). Attention output is written
// in place into the q region, so one buffer suffices.
__device__ float g_qkv[(size_t)Mrows * QKVN];   // ~201 MB

// ---------------------------------------------------------------------------
// PTX helpers
// ---------------------------------------------------------------------------
__device__ __forceinline__ uint32_t smem_u32(const void* p) {
    return (uint32_t)__cvta_generic_to_shared(p);
}

__device__ __forceinline__ void ldsm4(uint32_t& r0, uint32_t& r1,
                                      uint32_t& r2, uint32_t& r3, uint32_t addr) {
    asm volatile("ldmatrix.sync.aligned.m8n8.x4.shared.b16 {%0,%1,%2,%3}, [%4];\n"
                 : "=r"(r0), "=r"(r1), "=r"(r2), "=r"(r3) : "r"(addr));
}

__device__ __forceinline__ void mma_bf16(float* c, const uint32_t* a, const uint32_t* b) {
    asm volatile(
        "mma.sync.aligned.m16n8k16.row.col.f32.bf16.bf16.f32 "
        "{%0,%1,%2,%3}, {%4,%5,%6,%7}, {%8,%9}, {%0,%1,%2,%3};\n"
        : "+f"(c[0]), "+f"(c[1]), "+f"(c[2]), "+f"(c[3])
        : "r"(a[0]), "r"(a[1]), "r"(a[2]), "r"(a[3]), "r"(b[0]), "r"(b[1]));
}

// split fp32 -> hi/lo bf16 (hi = rn(x), lo = rn(x - hi))
__device__ __forceinline__ void split_bf16(float v, __nv_bfloat16& h, __nv_bfloat16& l) {
    h = __float2bfloat16_rn(v);
    l = __float2bfloat16_rn(v - __bfloat162float(h));
}

// pack 4 bf16 into uint2
__device__ __forceinline__ uint2 pack4(__nv_bfloat16 a, __nv_bfloat16 b,
                                       __nv_bfloat16 c, __nv_bfloat16 d) {
    uint2 r;
    uint16_t ua = *(uint16_t*)&a, ub = *(uint16_t*)&b;
    uint16_t uc = *(uint16_t*)&c, ud = *(uint16_t*)&d;
    r.x = (uint32_t)ua | ((uint32_t)ub << 16);
    r.y = (uint32_t)uc | ((uint32_t)ud << 16);
    return r;
}

// ---------------------------------------------------------------------------
// bf16x3 tensor-core GEMM (NT): C[m][n] = sum_k A[m*lda+k] * W[n*Kdim+k] (+bias)
//   C ~= Ah*Wh + Ah*Wl + Al*Wh   (Al*Wl term ~2^-16, dropped)
// BM=BN=128, BK=16, 256 threads = 8 warps (4 m-rows x 2 n-cols),
// warp tile 32m x 64n via m16n8k16. Padded smem (LDT=24) -> conflict-free
// ldmatrix. Register prefetch of next k-tile. Requires M%128==N%128==K%16==0.
// ---------------------------------------------------------------------------
template <bool BIAS>
__global__ __launch_bounds__(256, 2)
void gemm_bf16x3(const float* __restrict__ A, const float* __restrict__ W,
                 const float* __restrict__ bias, float* __restrict__ C,
                 int Ndim, int Kdim, int lda)
{
    constexpr int BM = 128, BN = 128, BK = 16, LDT = 24;
    __shared__ __align__(16) __nv_bfloat16 Ah[BM][LDT], Al[BM][LDT];
    __shared__ __align__(16) __nv_bfloat16 Wh[BN][LDT], Wl[BN][LDT];

    const int tid  = threadIdx.x;
    const int lane = tid & 31;
    const int wid  = tid >> 5;
    const int wr   = wid >> 1;          // 0..3 -> m offset wr*32
    const int wc   = wid & 1;           // 0..1 -> n offset wc*64
    const int m0   = blockIdx.y * BM;
    const int n0   = blockIdx.x * BN;

    // global load mapping: 128 rows x 16 cols fp32 per tile, 2 rows/thread
    const int lrow = tid >> 2;          // 0..63
    const int lcol = (tid & 3) * 4;     // 0,4,8,12
    const float* Ag = A + (size_t)(m0 + lrow) * lda  + lcol;
    const float* Wg = W + (size_t)(n0 + lrow) * Kdim + lcol;

    float acc[2][8][4];
    #pragma unroll
    for (int i = 0; i < 2; ++i)
        #pragma unroll
        for (int j = 0; j < 8; ++j)
            #pragma unroll
            for (int e = 0; e < 4; ++e) acc[i][j][e] = 0.f;

    // ldmatrix base addresses (per-thread, fixed across k-loop)
    // A frag mi: tile t=lane>>3: row = wr*32 + mi*16 + (lane&7) + (t&1)*8, col=(t>>1)*8
    const int t    = lane >> 3;
    const int arow = (lane & 7) + (t & 1) * 8;
    const int acol = (t >> 1) * 8;
    uint32_t a_addr[2];
    #pragma unroll
    for (int mi = 0; mi < 2; ++mi)
        a_addr[mi] = smem_u32(&Ah[wr * 32 + mi * 16 + arow][acol]);
    const uint32_t a_lo_off = smem_u32(&Al[0][0]) - smem_u32(&Ah[0][0]);

    // B frag pair gi (covers n-groups 2gi,2gi+1):
    // n = wc*64 + gi*16 + (t>>1)*8 + (lane&7), col = (t&1)*8
    const int brow = (t >> 1) * 8 + (lane & 7);
    const int bcol = (t & 1) * 8;
    uint32_t b_addr[4];
    #pragma unroll
    for (int gi = 0; gi < 4; ++gi)
        b_addr[gi] = smem_u32(&Wh[wc * 64 + gi * 16 + brow][bcol]);
    const uint32_t b_lo_off = smem_u32(&Wl[0][0]) - smem_u32(&Wh[0][0]);

    // ---- load first k-tile to smem ----
    #pragma unroll
    for (int r = 0; r < 2; ++r) {
        const int row = lrow + r * 64;
        float4 a = *(const float4*)(Ag + (size_t)r * 64 * lda);
        float4 w = *(const float4*)(Wg + (size_t)r * 64 * Kdim);
        __nv_bfloat16 h0,h1,h2,h3,l0,l1,l2,l3;
        split_bf16(a.x,h0,l0); split_bf16(a.y,h1,l1);
        split_bf16(a.z,h2,l2); split_bf16(a.w,h3,l3);
        *(uint2*)&Ah[row][lcol] = pack4(h0,h1,h2,h3);
        *(uint2*)&Al[row][lcol] = pack4(l0,l1,l2,l3);
        split_bf16(w.x,h0,l0); split_bf16(w.y,h1,l1);
        split_bf16(w.z,h2,l2); split_bf16(w.w,h3,l3);
        *(uint2*)&Wh[row][lcol] = pack4(h0,h1,h2,h3);
        *(uint2*)&Wl[row][lcol] = pack4(l0,l1,l2,l3);
    }

    float4 pa[2], pw[2];

    for (int k0 = 0; k0 < Kdim; k0 += BK) {
        __syncthreads();

        const bool more = (k0 + BK) < Kdim;
        if (more) {
            #pragma unroll
            for (int r = 0; r < 2; ++r) {
                pa[r] = *(const float4*)(Ag + (size_t)r * 64 * lda  + k0 + BK);
                pw[r] = *(const float4*)(Wg + (size_t)r * 64 * Kdim + k0 + BK);
            }
        }

        uint32_t af[2][4], alf[2][4], bf[4][4];

        // pass 1: Ah x Wh
        #pragma unroll
        for (int mi = 0; mi < 2; ++mi)
            ldsm4(af[mi][0], af[mi][1], af[mi][2], af[mi][3], a_addr[mi]);
        #pragma unroll
        for (int gi = 0; gi < 4; ++gi)
            ldsm4(bf[gi][0], bf[gi][1], bf[gi][2], bf[gi][3], b_addr[gi]);
        #pragma unroll
        for (int mi = 0; mi < 2; ++mi)
            #pragma unroll
            for (int g = 0; g < 8; ++g)
                mma_bf16(acc[mi][g], af[mi], &bf[g >> 1][(g & 1) * 2]);

        // pass 2: Al x Wh
        #pragma unroll
        for (int mi = 0; mi < 2; ++mi)
            ldsm4(alf[mi][0], alf[mi][1], alf[mi][2], alf[mi][3], a_addr[mi] + a_lo_off);
        #pragma unroll
        for (int mi = 0; mi < 2; ++mi)
            #pragma unroll
            for (int g = 0; g < 8; ++g)
                mma_bf16(acc[mi][g], alf[mi], &bf[g >> 1][(g & 1) * 2]);

        // pass 3: Ah x Wl (reuse bf regs)
        #pragma unroll
        for (int gi = 0; gi < 4; ++gi)
            ldsm4(bf[gi][0], bf[gi][1], bf[gi][2], bf[gi][3], b_addr[gi] + b_lo_off);
        #pragma unroll
        for (int mi = 0; mi < 2; ++mi)
            #pragma unroll
            for (int g = 0; g < 8; ++g)
                mma_bf16(acc[mi][g], af[mi], &bf[g >> 1][(g & 1) * 2]);

        __syncthreads();

        if (more) {
            #pragma unroll
            for (int r = 0; r < 2; ++r) {
                const int row = lrow + r * 64;
                __nv_bfloat16 h0,h1,h2,h3,l0,l1,l2,l3;
                split_bf16(pa[r].x,h0,l0); split_bf16(pa[r].y,h1,l1);
                split_bf16(pa[r].z,h2,l2); split_bf16(pa[r].w,h3,l3);
                *(uint2*)&Ah[row][lcol] = pack4(h0,h1,h2,h3);
                *(uint2*)&Al[row][lcol] = pack4(l0,l1,l2,l3);
                split_bf16(pw[r].x,h0,l0); split_bf16(pw[r].y,h1,l1);
                split_bf16(pw[r].z,h2,l2); split_bf16(pw[r].w,h3,l3);
                *(uint2*)&Wh[row][lcol] = pack4(h0,h1,h2,h3);
                *(uint2*)&Wl[row][lcol] = pack4(l0,l1,l2,l3);
            }
        }
    }

    // ---- epilogue: c frag -> global (+bias) ----
    const int crow = lane >> 2;           // 0..7
    const int ccol = (lane & 3) * 2;      // 0,2,4,6
    #pragma unroll
    for (int mi = 0; mi < 2; ++mi) {
        #pragma unroll
        for (int g = 0; g < 8; ++g) {
            const int col = n0 + wc * 64 + g * 8 + ccol;
            float b0 = BIAS ? bias[col]     : 0.f;
            float b1 = BIAS ? bias[col + 1] : 0.f;
            const int r0 = m0 + wr * 32 + mi * 16 + crow;
            float2 v0 = make_float2(acc[mi][g][0] + b0, acc[mi][g][1] + b1);
            float2 v1 = make_float2(acc[mi][g][2] + b0, acc[mi][g][3] + b1);
            *(float2*)(C + (size_t)r0 * Ndim + col)       = v0;
            *(float2*)(C + (size_t)(r0 + 8) * Ndim + col) = v1;
        }
    }
}

// ---------------------------------------------------------------------------
// Attention (the "faithful reshape" 16x16 head-mixing), in place into q region.
//   q_prep[b, n, h, dh] = q[b, h*256 + n/16, (n%16)*64 + dh]
//   scores = q.k^T/8, softmax over g, attn = probs.v, written back over q.
// One CTA per (b, r); CTA (b,r) uniquely owns rows {b, hh*256 + r}.
// ---------------------------------------------------------------------------
__global__ __launch_bounds__(256)
void attn16_kernel(float* __restrict__ qkv)
{
    const int b = blockIdx.x >> 8;
    const int r = blockIdx.x & 255;
    const int tid = threadIdx.x;
    const int hh = tid >> 4;
    const int lo = tid & 15;

    __shared__ float qs[16][64];
    __shared__ float ks[16][65];
    __shared__ float vs[16][64];
    __shared__ float ps[16][17];

    const size_t rowbase = ((size_t)b * 4096 + (size_t)hh * 256 + r) * 3072;
    const float scale = 0.125f;

    for (int j = 0; j < 16; ++j) {
        {
            const size_t c = (size_t)j * 64 + lo * 4;
            float4 q4 = *(const float4*)(qkv + rowbase + 0    + c);
            float4 k4 = *(const float4*)(qkv + rowbase + 1024 + c);
            float4 v4 = *(const float4*)(qkv + rowbase + 2048 + c);
            *(float4*)&qs[hh][lo * 4] = q4;
            ks[hh][lo * 4 + 0] = k4.x; ks[hh][lo * 4 + 1] = k4.y;
            ks[hh][lo * 4 + 2] = k4.z; ks[hh][lo * 4 + 3] = k4.w;
            *(float4*)&vs[hh][lo * 4] = v4;
        }
        __syncthreads();

        float s = 0.f;
        #pragma unroll
        for (int d = 0; d < 64; ++d) s = fmaf(qs[hh][d], ks[lo][d], s);
        s *= scale;

        float mx = s;
        #pragma unroll
        for (int off = 8; off; off >>= 1)
            mx = fmaxf(mx, __shfl_xor_sync(0xffffffffu, mx, off, 16));
        float e = __expf(s - mx);
        float sum = e;
        #pragma unroll
        for (int off = 8; off; off >>= 1)
            sum += __shfl_xor_sync(0xffffffffu, sum, off, 16);
        ps[hh][lo] = e / sum;
        __syncthreads();

        float4 o = make_float4(0.f, 0.f, 0.f, 0.f);
        #pragma unroll
        for (int g = 0; g < 16; ++g) {
            const float p = ps[hh][g];
            float4 v4 = *(const float4*)&vs[g][lo * 4];
            o.x = fmaf(p, v4.x, o.x); o.y = fmaf(p, v4.y, o.y);
            o.z = fmaf(p, v4.z, o.z); o.w = fmaf(p, v4.w, o.w);
        }
        *(float4*)(qkv + rowbase + (size_t)j * 64 + lo * 4) = o;
        __syncthreads();
    }
}

// ---------------------------------------------------------------------------
// Launch
// ---------------------------------------------------------------------------
extern "C" void kernel_launch(void* const* d_in, const int* in_sizes, int n_in,
                              void* d_out, int out_size)
{
    const float* x     = (const float*)d_in[0];  // (4, 4096, 1024)
    const float* w_qkv = (const float*)d_in[1];  // (3072, 1024)
    const float* w_fc  = (const float*)d_in[2];  // (1024, 1024)
    const float* b_fc  = (const float*)d_in[3];  // (1024,)
    float* out = (float*)d_out;                  // (4, 4096, 1024)

    float* qkv_ptr = nullptr;
    cudaGetSymbolAddress((void**)&qkv_ptr, g_qkv);

    dim3 blk(256);

    // 1) qkv = x @ w_qkv^T : M=16384, N=3072, K=1024, lda=1024
    gemm_bf16x3<false><<<dim3(QKVN / 128, Mrows / 128), blk>>>(
        x, w_qkv, nullptr, qkv_ptr, QKVN, Dd, Dd);

    // 2) scrambled 16x16 head-mix attention, in place into q region
    attn16_kernel<<<Bb * 256, blk>>>(qkv_ptr);

    // 3) out = attn @ w_fc^T + b_fc : M=16384, N=1024, K=1024, lda=3072
    gemm_bf16x3<true><<<dim3(Dd / 128, Mrows / 128), blk>>>(
        qkv_ptr, w_fc, b_fc, out, Dd, Dd, QKVN);
}

// round 6
// speedup vs baseline: 2.8065x; 1.1302x over previous
#include <cuda_runtime.h>
#include <cuda_bf16.h>
#include <cstddef>
#include <cstdint>

using bf16 = __nv_bfloat16;

// Problem constants
static constexpr int Bb    = 4;
static constexpr int Nn    = 4096;
static constexpr int Dd    = 1024;
static constexpr int Mrows = Bb * Nn;      // 16384
static constexpr int QKVN  = 3 * Dd;       // 3072
static constexpr int Kdim  = 1024;         // K of both GEMMs

// ---------------------------------------------------------------------------
// Scratch (__device__ globals; allocation-free rule)
// ---------------------------------------------------------------------------
__device__ float g_qkv[(size_t)Mrows * QKVN];          // fp32 qkv
__device__ bf16  g_xh [(size_t)Mrows * Dd], g_xl [(size_t)Mrows * Dd];
__device__ bf16  g_ah [(size_t)Mrows * Dd], g_al [(size_t)Mrows * Dd];
__device__ bf16  g_wqh[(size_t)QKVN  * Dd], g_wql[(size_t)QKVN  * Dd];
__device__ bf16  g_wfh[(size_t)Dd    * Dd], g_wfl[(size_t)Dd    * Dd];

// ---------------------------------------------------------------------------
// Helpers
// ---------------------------------------------------------------------------
__device__ __forceinline__ uint32_t smem_u32(const void* p) {
    return (uint32_t)__cvta_generic_to_shared(p);
}
__device__ __forceinline__ void ldsm4(uint32_t& r0, uint32_t& r1,
                                      uint32_t& r2, uint32_t& r3, uint32_t addr) {
    asm volatile("ldmatrix.sync.aligned.m8n8.x4.shared.b16 {%0,%1,%2,%3}, [%4];\n"
                 : "=r"(r0), "=r"(r1), "=r"(r2), "=r"(r3) : "r"(addr));
}
__device__ __forceinline__ void mma_bf16(float* c, const uint32_t* a, const uint32_t* b) {
    asm volatile(
        "mma.sync.aligned.m16n8k16.row.col.f32.bf16.bf16.f32 "
        "{%0,%1,%2,%3}, {%4,%5,%6,%7}, {%8,%9}, {%0,%1,%2,%3};\n"
        : "+f"(c[0]), "+f"(c[1]), "+f"(c[2]), "+f"(c[3])
        : "r"(a[0]), "r"(a[1]), "r"(a[2]), "r"(a[3]), "r"(b[0]), "r"(b[1]));
}
__device__ __forceinline__ void cp16(uint32_t dst, const void* src) {
    asm volatile("cp.async.cg.shared.global [%0], [%1], 16;" :: "r"(dst), "l"(src));
}
__device__ __forceinline__ void cp_commit() {
    asm volatile("cp.async.commit_group;" ::: "memory");
}
template <int N>
__device__ __forceinline__ void cp_wait() {
    asm volatile("cp.async.wait_group %0;" :: "n"(N) : "memory");
}
__device__ __forceinline__ void split_bf16(float v, bf16& h, bf16& l) {
    h = __float2bfloat16_rn(v);
    l = __float2bfloat16_rn(v - __bfloat162float(h));
}
__device__ __forceinline__ uint2 pack4(bf16 a, bf16 b, bf16 c, bf16 d) {
    uint2 r;
    uint16_t ua = *(uint16_t*)&a, ub = *(uint16_t*)&b;
    uint16_t uc = *(uint16_t*)&c, ud = *(uint16_t*)&d;
    r.x = (uint32_t)ua | ((uint32_t)ub << 16);
    r.y = (uint32_t)uc | ((uint32_t)ud << 16);
    return r;
}

// ---------------------------------------------------------------------------
// bf16x3 tensor-core GEMM (NT), cp.async 3-stage pipeline.
//   C[m][n] = sum_k A[m][k]*W[n][k] (+bias),  C ~= Ah*Wh + Al*Wh + Ah*Wl
// Inputs pre-split hi/lo bf16, K-major, K=1024. CTA 128x128, BK=32,
// 8 warps (4m x 2n), warp tile 32m x 64n, m16n8k16.
// smem layout per stage: [Ah | Al | Wh | Wl], each 128 rows x 64 B,
// XOR swizzle: chunk' = chunk ^ ((row>>1)&3)  (16 B chunks, 4 per row).
// Conflict-free for cp.async stores and ldmatrix reads (verified bank math).
// ---------------------------------------------------------------------------
static constexpr int BK      = 32;
static constexpr int KTILES  = Kdim / BK;        // 32
static constexpr int TSZ     = 128 * 64;          // 8192 B per array tile
static constexpr int STAGE   = 4 * TSZ;           // 32768 B
static constexpr int NSTAGE  = 3;
static constexpr int SMEM_TOTAL = NSTAGE * STAGE; // 98304 B

template <bool BIAS>
__global__ __launch_bounds__(256, 2)
void gemm_cp(const bf16* __restrict__ Ah, const bf16* __restrict__ Al,
             const bf16* __restrict__ Wh, const bf16* __restrict__ Wl,
             const float* __restrict__ bias, float* __restrict__ C, int Ndim)
{
    extern __shared__ char smem[];
    const uint32_t smem_base = smem_u32(smem);
    const int tid  = threadIdx.x;
    const int wid  = tid >> 5;
    const int lane = tid & 31;
    const int wr   = wid & 3;           // m offset wr*32
    const int wc   = wid >> 2;          // n offset wc*64
    const int m0   = blockIdx.y * 128;
    const int n0   = blockIdx.x * 128;

    const bf16* src[4] = { Ah + (size_t)m0 * Kdim, Al + (size_t)m0 * Kdim,
                           Wh + (size_t)n0 * Kdim, Wl + (size_t)n0 * Kdim };

    // ---- cp.async mapping (per thread: 8 chunks of 16 B per stage) ----
    // idx = tid + i*256 in [0,2048): arr = idx>>9, row = (idx&511)>>2, ch = idx&3
    auto load_stage = [&](int t, int buf) {
        const int k0 = t * BK;
        const uint32_t sb = smem_base + buf * STAGE;
        #pragma unroll
        for (int i = 0; i < 8; ++i) {
            const int idx = tid + i * 256;
            const int arr = idx >> 9;
            const int id2 = idx & 511;
            const int row = id2 >> 2;
            const int ch  = id2 & 3;
            const uint32_t dst = sb + arr * TSZ + row * 64 +
                                 ((ch ^ ((row >> 1) & 3)) << 4);
            cp16(dst, src[arr] + (size_t)row * Kdim + k0 + ch * 8);
        }
        cp_commit();
    };

    // ---- ldmatrix offsets (within stage), per mi/gi and k-step ----
    const int tq   = lane >> 3;
    const int arow = (lane & 7) + (tq & 1) * 8;
    const int ach  = tq >> 1;                   // A chunk base (0/1)
    const int brow = (tq >> 1) * 8 + (lane & 7);
    const int bch  = tq & 1;                    // B chunk base (0/1)

    uint32_t offA[2][2], offB[4][2];
    #pragma unroll
    for (int mi = 0; mi < 2; ++mi) {
        const int row = wr * 32 + mi * 16 + arow;
        #pragma unroll
        for (int ks = 0; ks < 2; ++ks) {
            const int ch = ach + ks * 2;
            offA[mi][ks] = row * 64 + (((ch ^ ((row >> 1) & 3))) << 4);
        }
    }
    #pragma unroll
    for (int gi = 0; gi < 4; ++gi) {
        const int row = wc * 64 + gi * 16 + brow;
        #pragma unroll
        for (int ks = 0; ks < 2; ++ks) {
            const int ch = bch + ks * 2;
            offB[gi][ks] = row * 64 + (((ch ^ ((row >> 1) & 3))) << 4);
        }
    }

    float acc[2][8][4];
    #pragma unroll
    for (int i = 0; i < 2; ++i)
        #pragma unroll
        for (int j = 0; j < 8; ++j)
            #pragma unroll
            for (int e = 0; e < 4; ++e) acc[i][j][e] = 0.f;

    // ---- prologue: fill the pipeline ----
    load_stage(0, 0);
    load_stage(1, 1);
    load_stage(2, 2);

    for (int t = 0; t < KTILES; ++t) {
        cp_wait<2>();              // stage t landed
        __syncthreads();

        const int buf = t % NSTAGE;
        const uint32_t sa = smem_base + buf * STAGE;            // Ah base
        const uint32_t sw = sa + 2 * TSZ;                       // Wh base

        #pragma unroll
        for (int ks = 0; ks < 2; ++ks) {
            uint32_t af[2][4], alf[2][4], bfr[4][4];
            // pass 1: Ah x Wh
            #pragma unroll
            for (int mi = 0; mi < 2; ++mi)
                ldsm4(af[mi][0], af[mi][1], af[mi][2], af[mi][3], sa + offA[mi][ks]);
            #pragma unroll
            for (int gi = 0; gi < 4; ++gi)
                ldsm4(bfr[gi][0], bfr[gi][1], bfr[gi][2], bfr[gi][3], sw + offB[gi][ks]);
            #pragma unroll
            for (int mi = 0; mi < 2; ++mi)
                #pragma unroll
                for (int g = 0; g < 8; ++g)
                    mma_bf16(acc[mi][g], af[mi], &bfr[g >> 1][(g & 1) * 2]);
            // pass 2: Al x Wh
            #pragma unroll
            for (int mi = 0; mi < 2; ++mi)
                ldsm4(alf[mi][0], alf[mi][1], alf[mi][2], alf[mi][3],
                      sa + TSZ + offA[mi][ks]);
            #pragma unroll
            for (int mi = 0; mi < 2; ++mi)
                #pragma unroll
                for (int g = 0; g < 8; ++g)
                    mma_bf16(acc[mi][g], alf[mi], &bfr[g >> 1][(g & 1) * 2]);
            // pass 3: Ah x Wl
            #pragma unroll
            for (int gi = 0; gi < 4; ++gi)
                ldsm4(bfr[gi][0], bfr[gi][1], bfr[gi][2], bfr[gi][3],
                      sw + TSZ + offB[gi][ks]);
            #pragma unroll
            for (int mi = 0; mi < 2; ++mi)
                #pragma unroll
                for (int g = 0; g < 8; ++g)
                    mma_bf16(acc[mi][g], af[mi], &bfr[g >> 1][(g & 1) * 2]);
        }

        __syncthreads();
        if (t + NSTAGE < KTILES) load_stage(t + NSTAGE, buf);
    }

    // ---- epilogue (m16n8 C-frag layout) ----
    const int crow = lane >> 2;           // 0..7
    const int ccol = (lane & 3) * 2;      // 0,2,4,6
    #pragma unroll
    for (int mi = 0; mi < 2; ++mi) {
        #pragma unroll
        for (int g = 0; g < 8; ++g) {
            const int col = n0 + wc * 64 + g * 8 + ccol;
            float b0 = BIAS ? bias[col]     : 0.f;
            float b1 = BIAS ? bias[col + 1] : 0.f;
            const int r0 = m0 + wr * 32 + mi * 16 + crow;
            float2 v0 = make_float2(acc[mi][g][0] + b0, acc[mi][g][1] + b1);
            float2 v1 = make_float2(acc[mi][g][2] + b0, acc[mi][g][3] + b1);
            *(float2*)(C + (size_t)r0 * Ndim + col)       = v0;
            *(float2*)(C + (size_t)(r0 + 8) * Ndim + col) = v1;
        }
    }
}

// ---------------------------------------------------------------------------
// fp32 -> hi/lo bf16 split (element-wise)
// ---------------------------------------------------------------------------
__global__ void convert_split(const float* __restrict__ src, bf16* __restrict__ h,
                              bf16* __restrict__ l, int n4)
{
    const int i = blockIdx.x * blockDim.x + threadIdx.x;
    if (i >= n4) return;
    float4 v = *(const float4*)(src + (size_t)i * 4);
    bf16 h0,h1,h2,h3,l0,l1,l2,l3;
    split_bf16(v.x,h0,l0); split_bf16(v.y,h1,l1);
    split_bf16(v.z,h2,l2); split_bf16(v.w,h3,l3);
    *(uint2*)(h + (size_t)i * 4) = pack4(h0,h1,h2,h3);
    *(uint2*)(l + (size_t)i * 4) = pack4(l0,l1,l2,l3);
}

// ---------------------------------------------------------------------------
// Attention (faithful-reshape 16x16 head-mixing): fp32 qkv in, hi/lo bf16 out.
//   q_prep[b, n, h, dh] = q[b, h*256 + n/16, (n%16)*64 + dh]
// One CTA per (b, r=n/16); CTA uniquely owns rows {b, hh*256 + r}.
// ---------------------------------------------------------------------------
__global__ __launch_bounds__(256)
void attn16_kernel(const float* __restrict__ qkv,
                   bf16* __restrict__ oh, bf16* __restrict__ ol)
{
    const int b = blockIdx.x >> 8;
    const int r = blockIdx.x & 255;
    const int tid = threadIdx.x;
    const int hh = tid >> 4;
    const int lo = tid & 15;

    __shared__ float qs[16][64];
    __shared__ float ks[16][65];
    __shared__ float vs[16][64];
    __shared__ float ps[16][17];

    const size_t rowbase = ((size_t)b * 4096 + (size_t)hh * 256 + r) * 3072;
    const size_t outbase = ((size_t)b * 4096 + (size_t)hh * 256 + r) * 1024;
    const float scale = 0.125f;

    for (int j = 0; j < 16; ++j) {
        {
            const size_t c = (size_t)j * 64 + lo * 4;
            float4 q4 = *(const float4*)(qkv + rowbase + 0    + c);
            float4 k4 = *(const float4*)(qkv + rowbase + 1024 + c);
            float4 v4 = *(const float4*)(qkv + rowbase + 2048 + c);
            *(float4*)&qs[hh][lo * 4] = q4;
            ks[hh][lo * 4 + 0] = k4.x; ks[hh][lo * 4 + 1] = k4.y;
            ks[hh][lo * 4 + 2] = k4.z; ks[hh][lo * 4 + 3] = k4.w;
            *(float4*)&vs[hh][lo * 4] = v4;
        }
        __syncthreads();

        float s = 0.f;
        #pragma unroll
        for (int d = 0; d < 64; ++d) s = fmaf(qs[hh][d], ks[lo][d], s);
        s *= scale;

        float mx = s;
        #pragma unroll
        for (int off = 8; off; off >>= 1)
            mx = fmaxf(mx, __shfl_xor_sync(0xffffffffu, mx, off, 16));
        float e = __expf(s - mx);
        float sum = e;
        #pragma unroll
        for (int off = 8; off; off >>= 1)
            sum += __shfl_xor_sync(0xffffffffu, sum, off, 16);
        ps[hh][lo] = e / sum;
        __syncthreads();

        float4 o = make_float4(0.f, 0.f, 0.f, 0.f);
        #pragma unroll
        for (int g = 0; g < 16; ++g) {
            const float p = ps[hh][g];
            float4 v4 = *(const float4*)&vs[g][lo * 4];
            o.x = fmaf(p, v4.x, o.x); o.y = fmaf(p, v4.y, o.y);
            o.z = fmaf(p, v4.z, o.z); o.w = fmaf(p, v4.w, o.w);
        }
        bf16 h0,h1,h2,h3,l0,l1,l2,l3;
        split_bf16(o.x,h0,l0); split_bf16(o.y,h1,l1);
        split_bf16(o.z,h2,l2); split_bf16(o.w,h3,l3);
        *(uint2*)(oh + outbase + (size_t)j * 64 + lo * 4) = pack4(h0,h1,h2,h3);
        *(uint2*)(ol + outbase + (size_t)j * 64 + lo * 4) = pack4(l0,l1,l2,l3);
        __syncthreads();
    }
}

// ---------------------------------------------------------------------------
// Launch
// ---------------------------------------------------------------------------
extern "C" void kernel_launch(void* const* d_in, const int* in_sizes, int n_in,
                              void* d_out, int out_size)
{
    const float* x     = (const float*)d_in[0];  // (4, 4096, 1024)
    const float* w_qkv = (const float*)d_in[1];  // (3072, 1024)
    const float* w_fc  = (const float*)d_in[2];  // (1024, 1024)
    const float* b_fc  = (const float*)d_in[3];  // (1024,)
    float* out = (float*)d_out;                  // (4, 4096, 1024)

    float *qkv_p; bf16 *xh_p, *xl_p, *ah_p, *al_p, *wqh_p, *wql_p, *wfh_p, *wfl_p;
    cudaGetSymbolAddress((void**)&qkv_p, g_qkv);
    cudaGetSymbolAddress((void**)&xh_p,  g_xh);  cudaGetSymbolAddress((void**)&xl_p,  g_xl);
    cudaGetSymbolAddress((void**)&ah_p,  g_ah);  cudaGetSymbolAddress((void**)&al_p,  g_al);
    cudaGetSymbolAddress((void**)&wqh_p, g_wqh); cudaGetSymbolAddress((void**)&wql_p, g_wql);
    cudaGetSymbolAddress((void**)&wfh_p, g_wfh); cudaGetSymbolAddress((void**)&wfl_p, g_wfl);

    cudaFuncSetAttribute(gemm_cp<false>, cudaFuncAttributeMaxDynamicSharedMemorySize, SMEM_TOTAL);
    cudaFuncSetAttribute(gemm_cp<true>,  cudaFuncAttributeMaxDynamicSharedMemorySize, SMEM_TOTAL);

    // 0) split inputs/weights into hi/lo bf16
    {
        int n4 = Mrows * Dd / 4;
        convert_split<<<(n4 + 255) / 256, 256>>>(x, xh_p, xl_p, n4);
        n4 = QKVN * Dd / 4;
        convert_split<<<(n4 + 255) / 256, 256>>>(w_qkv, wqh_p, wql_p, n4);
        n4 = Dd * Dd / 4;
        convert_split<<<(n4 + 255) / 256, 256>>>(w_fc, wfh_p, wfl_p, n4);
    }

    // 1) qkv = x @ w_qkv^T  (fp32 out, M=16384, N=3072)
    gemm_cp<false><<<dim3(QKVN / 128, Mrows / 128), 256, SMEM_TOTAL>>>(
        xh_p, xl_p, wqh_p, wql_p, nullptr, qkv_p, QKVN);

    // 2) 16x16 head-mix attention -> hi/lo bf16
    attn16_kernel<<<Bb * 256, 256>>>(qkv_p, ah_p, al_p);

    // 3) out = attn @ w_fc^T + b_fc  (M=16384, N=1024)
    gemm_cp<true><<<dim3(Dd / 128, Mrows / 128), 256, SMEM_TOTAL>>>(
        ah_p, al_p, wfh_p, wfl_p, b_fc, out, Dd);
}